// round 1
// baseline (speedup 1.0000x reference)
#include <cuda_runtime.h>

// ---------------------------------------------------------------------------
// FCHCGNN: 3-layer GCN (GCNConv with self-loops + symmetric norm) + log_softmax
//   N = 100000 nodes, E = 1600000 edges, dims 128 -> 128 -> 128 -> 64
//
// Stages per layer:
//   t = X @ W                    (fp32 SGEMM, W resident in smem)
//   a = 0
//   a[dst] += t[src] * norm[e]   (vector red.global.add.v4.f32)
//   out = relu(a + t * dis^2 + b)   (self-loop folded in analytically)
// Then row-wise log_softmax over 64 cols.
// ---------------------------------------------------------------------------

#define NN_MAX 100000
#define EE_MAX 1600000

__device__ float g_t[(size_t)NN_MAX * 128];
__device__ float g_h[(size_t)NN_MAX * 128];
__device__ float g_a[(size_t)NN_MAX * 128];
__device__ float g_deg[NN_MAX];
__device__ float g_dis[NN_MAX];
__device__ float g_norm[EE_MAX];

// ------------------------- degree / norm precompute -------------------------

__global__ void init_deg_kernel(float* __restrict__ deg, int n) {
    int i = blockIdx.x * blockDim.x + threadIdx.x;
    if (i < n) deg[i] = 1.0f;  // self-loop contributes 1 to every node's degree
}

__global__ void count_deg_kernel(const int* __restrict__ dst, float* deg, int e) {
    int i = blockIdx.x * blockDim.x + threadIdx.x;
    if (i < e) atomicAdd(&deg[dst[i]], 1.0f);
}

__global__ void dis_kernel(const float* __restrict__ deg, float* __restrict__ dis, int n) {
    int i = blockIdx.x * blockDim.x + threadIdx.x;
    if (i < n) dis[i] = rsqrtf(deg[i]);  // deg >= 1 always
}

__global__ void norm_kernel(const int* __restrict__ src, const int* __restrict__ dst,
                            const float* __restrict__ dis, float* __restrict__ nrm, int e) {
    int i = blockIdx.x * blockDim.x + threadIdx.x;
    if (i < e) nrm[i] = dis[src[i]] * dis[dst[i]];
}

// ------------------------------- SGEMM ---------------------------------
// X: [n,128] row-major.  W: [128,FOUT] row-major.  T = X@W : [n,FOUT].
// Block: 128 rows x FOUT cols, 256 threads, 8x(FOUT/16) register tile/thread.
// W held fully in smem; X streamed in K-tiles of 32 with padded stride.

template <int FOUT>
__global__ void gemm_kernel(const float* __restrict__ X, const float* __restrict__ W,
                            float* __restrict__ T, int n) {
    constexpr int KT = 32;
    constexpr int XS = KT + 2;       // pad: delta-8-rows -> 8*34 % 32 = 16 (no conflicts)
    constexpr int CPT = FOUT / 16;   // cols per thread (8 or 4)
    extern __shared__ float smem[];
    float* Ws = smem;                // [128][FOUT]
    float* Xs = smem + 128 * FOUT;   // [128][XS]

    const int tid  = threadIdx.x;
    const int row0 = blockIdx.x * 128;

    for (int i = tid; i < 128 * FOUT / 4; i += 256)
        ((float4*)Ws)[i] = ((const float4*)W)[i];

    const int ty = tid >> 4;   // 0..15 row group
    const int tx = tid & 15;   // 0..15 col group

    float acc[8][CPT];
#pragma unroll
    for (int i = 0; i < 8; i++)
#pragma unroll
        for (int j = 0; j < CPT; j++) acc[i][j] = 0.0f;

#pragma unroll 1
    for (int k0 = 0; k0 < 128; k0 += KT) {
        __syncthreads();
        // load X tile: 128 rows x KT cols (float4 global load, scalar smem store)
#pragma unroll
        for (int i = tid; i < 128 * (KT / 4); i += 256) {
            int r = i >> 3, c4 = i & 7;
            int gr = row0 + r;
            float4 v = make_float4(0.f, 0.f, 0.f, 0.f);
            if (gr < n) v = *(const float4*)&X[(size_t)gr * 128 + k0 + c4 * 4];
            float* p = &Xs[r * XS + c4 * 4];
            p[0] = v.x; p[1] = v.y; p[2] = v.z; p[3] = v.w;
        }
        __syncthreads();
#pragma unroll
        for (int kk = 0; kk < KT; kk++) {
            float xv[8];
#pragma unroll
            for (int i = 0; i < 8; i++) xv[i] = Xs[(ty * 8 + i) * XS + kk];
            float wv[CPT];
            {
                float4 w0 = *(const float4*)&Ws[(k0 + kk) * FOUT + tx * CPT];
                wv[0] = w0.x; wv[1] = w0.y; wv[2] = w0.z; wv[3] = w0.w;
                if constexpr (CPT == 8) {
                    float4 w1 = *(const float4*)&Ws[(k0 + kk) * FOUT + tx * CPT + 4];
                    wv[4] = w1.x; wv[5] = w1.y; wv[6] = w1.z; wv[7] = w1.w;
                }
            }
#pragma unroll
            for (int i = 0; i < 8; i++)
#pragma unroll
                for (int j = 0; j < CPT; j++)
                    acc[i][j] = fmaf(xv[i], wv[j], acc[i][j]);
        }
    }

#pragma unroll
    for (int i = 0; i < 8; i++) {
        int gr = row0 + ty * 8 + i;
        if (gr < n) {
            float4 o0;
            o0.x = acc[i][0]; o0.y = acc[i][1]; o0.z = acc[i][2]; o0.w = acc[i][3];
            *(float4*)&T[(size_t)gr * FOUT + tx * CPT] = o0;
            if constexpr (CPT == 8) {
                float4 o1;
                o1.x = acc[i][4]; o1.y = acc[i][5]; o1.z = acc[i][6]; o1.w = acc[i][7];
                *(float4*)&T[(size_t)gr * FOUT + tx * CPT + 4] = o1;
            }
        }
    }
}

// ------------------------------ edge scatter --------------------------------
// One thread per (edge, float4-chunk). Gather t[src], scale, 16B vector
// reduction into a[dst]. For F=128 a warp covers exactly one edge.

template <int F>
__global__ void scatter_kernel(const float* __restrict__ T, const int* __restrict__ src,
                               const int* __restrict__ dst, const float* __restrict__ nrm,
                               float* __restrict__ A, int e) {
    constexpr int V = F / 4;
    int gid = blockIdx.x * blockDim.x + threadIdx.x;
    int ed = gid / V;
    int f  = gid % V;
    if (ed >= e) return;
    int s = src[ed];
    int d = dst[ed];
    float w = nrm[ed];
    float4 v = *(const float4*)&T[(size_t)s * F + f * 4];
    float* p = A + (size_t)d * F + f * 4;
    asm volatile("red.global.add.v4.f32 [%0], {%1,%2,%3,%4};"
                 :: "l"(p), "f"(v.x * w), "f"(v.y * w), "f"(v.z * w), "f"(v.w * w)
                 : "memory");
}

// -------------------------- self-loop + bias + relu -------------------------

template <int F>
__global__ void finalize_kernel(const float* __restrict__ A, const float* __restrict__ T,
                                const float* __restrict__ dis, const float* __restrict__ bias,
                                float* __restrict__ OUT, int n) {
    constexpr int V = F / 4;
    int gid = blockIdx.x * blockDim.x + threadIdx.x;
    if (gid >= n * V) return;
    int i = gid / V;
    int f = gid % V;
    float dd = dis[i];
    float sn = dd * dd;  // self-loop norm = dis[i]^2 = 1/deg[i]
    float4 a = *(const float4*)&A[(size_t)gid * 4];
    float4 t = *(const float4*)&T[(size_t)gid * 4];
    float4 b = *(const float4*)&bias[f * 4];
    float4 o;
    o.x = fmaxf(fmaf(t.x, sn, a.x) + b.x, 0.0f);
    o.y = fmaxf(fmaf(t.y, sn, a.y) + b.y, 0.0f);
    o.z = fmaxf(fmaf(t.z, sn, a.z) + b.z, 0.0f);
    o.w = fmaxf(fmaf(t.w, sn, a.w) + b.w, 0.0f);
    *(float4*)&OUT[(size_t)gid * 4] = o;
}

// ------------------------------ log_softmax ---------------------------------
// 64 columns per row: one warp per row, lane handles cols l and l+32.

__global__ void logsoftmax_kernel(const float* __restrict__ H, float* __restrict__ OUT, int n) {
    int row = blockIdx.x * 8 + (threadIdx.x >> 5);
    if (row >= n) return;
    int l = threadIdx.x & 31;
    const float* h = H + (size_t)row * 64;
    float a = h[l];
    float c = h[l + 32];
    float m = fmaxf(a, c);
#pragma unroll
    for (int o = 16; o; o >>= 1) m = fmaxf(m, __shfl_xor_sync(0xffffffffu, m, o));
    float s = expf(a - m) + expf(c - m);
#pragma unroll
    for (int o = 16; o; o >>= 1) s += __shfl_xor_sync(0xffffffffu, s, o);
    float lse = m + logf(s);
    float* ot = OUT + (size_t)row * 64;
    ot[l]      = a - lse;
    ot[l + 32] = c - lse;
}

// --------------------------------- driver -----------------------------------

extern "C" void kernel_launch(void* const* d_in, const int* in_sizes, int n_in,
                              void* d_out, int out_size) {
    const float* x  = (const float*)d_in[0];
    const int*   ei = (const int*)d_in[1];
    const float* W0 = (const float*)d_in[2];
    const float* b0 = (const float*)d_in[3];
    const float* W1 = (const float*)d_in[4];
    const float* b1 = (const float*)d_in[5];
    const float* W2 = (const float*)d_in[6];
    const float* b2 = (const float*)d_in[7];

    const int N = in_sizes[0] / 128;
    const int E = in_sizes[1] / 2;
    const int* src = ei;
    const int* dst = ei + E;

    float *t, *h, *a, *deg, *dis, *nrm;
    cudaGetSymbolAddress((void**)&t,   g_t);
    cudaGetSymbolAddress((void**)&h,   g_h);
    cudaGetSymbolAddress((void**)&a,   g_a);
    cudaGetSymbolAddress((void**)&deg, g_deg);
    cudaGetSymbolAddress((void**)&dis, g_dis);
    cudaGetSymbolAddress((void**)&nrm, g_norm);

    const int smem128 = 128 * 128 * 4 + 128 * 34 * 4;  // 82944 B
    const int smem64  = 128 * 64 * 4  + 128 * 34 * 4;  // 50176 B
    cudaFuncSetAttribute(gemm_kernel<128>, cudaFuncAttributeMaxDynamicSharedMemorySize, smem128);
    cudaFuncSetAttribute(gemm_kernel<64>,  cudaFuncAttributeMaxDynamicSharedMemorySize, smem64);

    // degree / normalization precompute
    init_deg_kernel<<<(N + 255) / 256, 256>>>(deg, N);
    count_deg_kernel<<<(E + 255) / 256, 256>>>(dst, deg, E);
    dis_kernel<<<(N + 255) / 256, 256>>>(deg, dis, N);
    norm_kernel<<<(E + 255) / 256, 256>>>(src, dst, dis, nrm, E);

    const int gblocks = (N + 127) / 128;

    // ----- layer 1: x(128) -> h(128) -----
    gemm_kernel<128><<<gblocks, 256, smem128>>>(x, W0, t, N);
    cudaMemsetAsync(a, 0, (size_t)N * 128 * sizeof(float));
    scatter_kernel<128><<<(E * 32 + 255) / 256, 256>>>(t, src, dst, nrm, a, E);
    finalize_kernel<128><<<(N * 32 + 255) / 256, 256>>>(a, t, dis, b0, h, N);

    // ----- layer 2: h(128) -> h(128) -----
    gemm_kernel<128><<<gblocks, 256, smem128>>>(h, W1, t, N);
    cudaMemsetAsync(a, 0, (size_t)N * 128 * sizeof(float));
    scatter_kernel<128><<<(E * 32 + 255) / 256, 256>>>(t, src, dst, nrm, a, E);
    finalize_kernel<128><<<(N * 32 + 255) / 256, 256>>>(a, t, dis, b1, h, N);

    // ----- layer 3: h(128) -> h(64) -----
    gemm_kernel<64><<<gblocks, 256, smem64>>>(h, W2, t, N);
    cudaMemsetAsync(a, 0, (size_t)N * 64 * sizeof(float));
    scatter_kernel<64><<<(E * 16 + 255) / 256, 256>>>(t, src, dst, nrm, a, E);
    finalize_kernel<64><<<(N * 16 + 255) / 256, 256>>>(a, t, dis, b2, h, N);

    // ----- log_softmax -----
    logsoftmax_kernel<<<(N + 7) / 8, 256>>>(h, (float*)d_out, N);
}

// round 3
// speedup vs baseline: 1.1041x; 1.1041x over previous
#include <cuda_runtime.h>

// ---------------------------------------------------------------------------
// FCHCGNN: 3-layer GCN + log_softmax, restructured:
//   1. Counting-sort edges by dst -> CSR (row_ptr, src_sorted, w_sorted)
//   2. Per layer: T = X@W (f32x2 packed-FMA SGEMM), then per-node segment
//      reduction over incoming edges (no atomics), fused self-loop+bias+relu.
//   3. Final layer fuses log_softmax into the reduction epilogue.
// ---------------------------------------------------------------------------

#define NN_MAX 100000
#define EE_MAX 1600000
#define SCAN_CHUNK 1024

__device__ float g_t[(size_t)NN_MAX * 128];
__device__ float g_h[(size_t)NN_MAX * 128];
__device__ float g_dis[NN_MAX];
__device__ int   g_rowptr[NN_MAX + 1];
__device__ int   g_cursor[NN_MAX];
__device__ int   g_srcs[EE_MAX];
__device__ float g_ws[EE_MAX];
__device__ int   g_bsums[128];

// --------------------------- CSR construction ------------------------------

__global__ void zero_kernel(int* __restrict__ p, int m) {
    int i = blockIdx.x * blockDim.x + threadIdx.x;
    if (i < m) p[i] = 0;
}

__global__ void hist_kernel(const int* __restrict__ dst, int* __restrict__ rp, int e) {
    int i = blockIdx.x * blockDim.x + threadIdx.x;
    if (i < e) atomicAdd(&rp[dst[i] + 1], 1);
}

// inclusive scan of chunks of SCAN_CHUNK, block totals to bsums
__global__ void scan1_kernel(int* __restrict__ data, int* __restrict__ bsums, int m) {
    __shared__ int s[SCAN_CHUNK];
    int tid = threadIdx.x;
    int i = blockIdx.x * SCAN_CHUNK + tid;
    int v = (i < m) ? data[i] : 0;
    s[tid] = v;
    __syncthreads();
#pragma unroll
    for (int o = 1; o < SCAN_CHUNK; o <<= 1) {
        int t = 0;
        if (tid >= o) t = s[tid - o];
        __syncthreads();
        s[tid] += t;
        __syncthreads();
    }
    if (i < m) data[i] = s[tid];
    if (tid == SCAN_CHUNK - 1) bsums[blockIdx.x] = s[SCAN_CHUNK - 1];
}

// single-block exclusive scan of block sums (m <= 128)
__global__ void scan2_kernel(int* __restrict__ bsums, int m) {
    __shared__ int s[128];
    int tid = threadIdx.x;
    int v = (tid < m) ? bsums[tid] : 0;
    s[tid] = v;
    __syncthreads();
#pragma unroll
    for (int o = 1; o < 128; o <<= 1) {
        int t = 0;
        if (tid >= o) t = s[tid - o];
        __syncthreads();
        s[tid] += t;
        __syncthreads();
    }
    if (tid < m) bsums[tid] = s[tid] - v;  // exclusive
}

__global__ void scan3_kernel(int* __restrict__ data, const int* __restrict__ bsums, int m) {
    int i = blockIdx.x * SCAN_CHUNK + threadIdx.x;
    if (i < m) data[i] += bsums[blockIdx.x];
}

__global__ void dis_kernel(const int* __restrict__ rp, float* __restrict__ dis, int n) {
    int i = blockIdx.x * blockDim.x + threadIdx.x;
    if (i < n) dis[i] = rsqrtf((float)(rp[i + 1] - rp[i] + 1));  // +1 self-loop
}

__global__ void cursor_kernel(const int* __restrict__ rp, int* __restrict__ cur, int n) {
    int i = blockIdx.x * blockDim.x + threadIdx.x;
    if (i < n) cur[i] = rp[i];
}

__global__ void bucket_kernel(const int* __restrict__ src, const int* __restrict__ dst,
                              const float* __restrict__ dis, int* __restrict__ cur,
                              int* __restrict__ srcs, float* __restrict__ ws, int e) {
    int i = blockIdx.x * blockDim.x + threadIdx.x;
    if (i < e) {
        int s = src[i], d = dst[i];
        int p = atomicAdd(&cur[d], 1);
        srcs[p] = s;
        ws[p] = dis[s] * dis[d];
    }
}

// ----------------------- SGEMM with packed f32x2 FMA ------------------------
// X: [n,128] row-major.  W: [128,FOUT].  T = X@W.
// Block covers 128 rows x FOUT cols with 256 threads; 8 rows x CPT cols/thread.
// Inner product uses fma.rn.f32x2 (FFMA2, sm_100+) -> 2 flops/FMA-issue.

template <int FOUT>
__global__ void gemm_kernel(const float* __restrict__ X, const float* __restrict__ W,
                            float* __restrict__ T, int n) {
    constexpr int KT = 32;
    constexpr int XS = KT + 2;
    constexpr int CPT = FOUT / 16;   // 8 or 4
    constexpr int CP2 = CPT / 2;     // col pairs
    extern __shared__ float smem[];
    float* Ws = smem;                // [128][FOUT]
    float* Xs = smem + 128 * FOUT;   // [128][XS]

    const int tid  = threadIdx.x;
    const int row0 = blockIdx.x * 128;

    for (int i = tid; i < 128 * FOUT / 4; i += 256)
        ((float4*)Ws)[i] = ((const float4*)W)[i];

    const int ty = tid >> 4;
    const int tx = tid & 15;

    unsigned long long acc[8][CP2];
#pragma unroll
    for (int i = 0; i < 8; i++)
#pragma unroll
        for (int j = 0; j < CP2; j++) acc[i][j] = 0ull;

#pragma unroll 1
    for (int k0 = 0; k0 < 128; k0 += KT) {
        __syncthreads();
#pragma unroll
        for (int i = tid; i < 128 * (KT / 4); i += 256) {
            int r = i >> 3, c4 = i & 7;
            int gr = row0 + r;
            float4 v = make_float4(0.f, 0.f, 0.f, 0.f);
            if (gr < n) v = *(const float4*)&X[(size_t)gr * 128 + k0 + c4 * 4];
            float* p = &Xs[r * XS + c4 * 4];
            p[0] = v.x; p[1] = v.y; p[2] = v.z; p[3] = v.w;
        }
        __syncthreads();
#pragma unroll
        for (int kk = 0; kk < KT; kk++) {
            unsigned long long wv[CP2];
            {
                ulonglong2 w0 = *(const ulonglong2*)&Ws[(k0 + kk) * FOUT + tx * CPT];
                wv[0] = w0.x; wv[1] = w0.y;
                if constexpr (CPT == 8) {
                    ulonglong2 w1 = *(const ulonglong2*)&Ws[(k0 + kk) * FOUT + tx * CPT + 4];
                    wv[2] = w1.x; wv[3] = w1.y;
                }
            }
#pragma unroll
            for (int i = 0; i < 8; i++) {
                float xv = Xs[(ty * 8 + i) * XS + kk];
                unsigned long long x2;
                asm("mov.b64 %0, {%1, %1};" : "=l"(x2) : "f"(xv));
#pragma unroll
                for (int j = 0; j < CP2; j++)
                    asm("fma.rn.f32x2 %0, %1, %2, %0;"
                        : "+l"(acc[i][j]) : "l"(x2), "l"(wv[j]));
            }
        }
    }

#pragma unroll
    for (int i = 0; i < 8; i++) {
        int gr = row0 + ty * 8 + i;
        if (gr < n) {
            *(ulonglong2*)&T[(size_t)gr * FOUT + tx * CPT] =
                make_ulonglong2(acc[i][0], acc[i][1]);
            if constexpr (CPT == 8)
                *(ulonglong2*)&T[(size_t)gr * FOUT + tx * CPT + 4] =
                    make_ulonglong2(acc[i][2], acc[i][3]);
        }
    }
}

// ---------------------- per-node segment reduction --------------------------
// One block per node, F threads (one per output column). Edges for this node
// are contiguous in CSR; staged through smem; no atomics anywhere.

template <int F>
__global__ void aggregate_kernel(const float* __restrict__ T, const int* __restrict__ rp,
                                 const int* __restrict__ srcs, const float* __restrict__ ws,
                                 const float* __restrict__ dis, const float* __restrict__ bias,
                                 float* __restrict__ OUT, int n) {
    __shared__ int   ss[F];
    __shared__ float sw[F];
    const int node = blockIdx.x;
    const int c = threadIdx.x;
    const int beg = rp[node], end = rp[node + 1];

    float a0 = 0.f, a1 = 0.f;
    for (int base = beg; base < end; base += F) {
        int cnt = min(F, end - base);
        if (c < cnt) { ss[c] = srcs[base + c]; sw[c] = ws[base + c]; }
        __syncthreads();
        int j = 0;
        for (; j + 1 < cnt; j += 2) {
            a0 = fmaf(__ldg(&T[(size_t)ss[j] * F + c]),     sw[j],     a0);
            a1 = fmaf(__ldg(&T[(size_t)ss[j + 1] * F + c]), sw[j + 1], a1);
        }
        if (j < cnt)
            a0 = fmaf(__ldg(&T[(size_t)ss[j] * F + c]), sw[j], a0);
        __syncthreads();
    }
    float dd = dis[node];
    float acc = a0 + a1;
    acc = fmaf(T[(size_t)node * F + c], dd * dd, acc) + bias[c];
    OUT[(size_t)node * F + c] = fmaxf(acc, 0.f);
}

// Final layer: segment reduction (F=64) with fused relu + log_softmax.
__global__ void aggregate_lsm_kernel(const float* __restrict__ T, const int* __restrict__ rp,
                                     const int* __restrict__ srcs, const float* __restrict__ ws,
                                     const float* __restrict__ dis, const float* __restrict__ bias,
                                     float* __restrict__ OUT, int n) {
    __shared__ int   ss[64];
    __shared__ float sw[64];
    __shared__ float xr[2];
    const int node = blockIdx.x;
    const int c = threadIdx.x;
    const int beg = rp[node], end = rp[node + 1];

    float a0 = 0.f, a1 = 0.f;
    for (int base = beg; base < end; base += 64) {
        int cnt = min(64, end - base);
        if (c < cnt) { ss[c] = srcs[base + c]; sw[c] = ws[base + c]; }
        __syncthreads();
        int j = 0;
        for (; j + 1 < cnt; j += 2) {
            a0 = fmaf(__ldg(&T[(size_t)ss[j] * 64 + c]),     sw[j],     a0);
            a1 = fmaf(__ldg(&T[(size_t)ss[j + 1] * 64 + c]), sw[j + 1], a1);
        }
        if (j < cnt)
            a0 = fmaf(__ldg(&T[(size_t)ss[j] * 64 + c]), sw[j], a0);
        __syncthreads();
    }
    float dd = dis[node];
    float acc = a0 + a1;
    acc = fmaf(T[(size_t)node * 64 + c], dd * dd, acc) + bias[c];
    acc = fmaxf(acc, 0.f);

    // log_softmax over the 64 columns (2 warps)
    float m = acc;
#pragma unroll
    for (int o = 16; o; o >>= 1) m = fmaxf(m, __shfl_xor_sync(0xffffffffu, m, o));
    if ((c & 31) == 0) xr[c >> 5] = m;
    __syncthreads();
    m = fmaxf(xr[0], xr[1]);
    __syncthreads();
    float s = expf(acc - m);
#pragma unroll
    for (int o = 16; o; o >>= 1) s += __shfl_xor_sync(0xffffffffu, s, o);
    if ((c & 31) == 0) xr[c >> 5] = s;
    __syncthreads();
    s = xr[0] + xr[1];
    OUT[(size_t)node * 64 + c] = acc - m - logf(s);
}

// --------------------------------- driver -----------------------------------

extern "C" void kernel_launch(void* const* d_in, const int* in_sizes, int n_in,
                              void* d_out, int out_size) {
    const float* x  = (const float*)d_in[0];
    const int*   ei = (const int*)d_in[1];
    const float* W0 = (const float*)d_in[2];
    const float* b0 = (const float*)d_in[3];
    const float* W1 = (const float*)d_in[4];
    const float* b1 = (const float*)d_in[5];
    const float* W2 = (const float*)d_in[6];
    const float* b2 = (const float*)d_in[7];

    const int N = in_sizes[0] / 128;
    const int E = in_sizes[1] / 2;
    const int* src = ei;
    const int* dst = ei + E;

    float *t, *h, *dis, *ws;
    int *rp, *cur, *srcs, *bsums;
    cudaGetSymbolAddress((void**)&t,     g_t);
    cudaGetSymbolAddress((void**)&h,     g_h);
    cudaGetSymbolAddress((void**)&dis,   g_dis);
    cudaGetSymbolAddress((void**)&rp,    g_rowptr);
    cudaGetSymbolAddress((void**)&cur,   g_cursor);
    cudaGetSymbolAddress((void**)&srcs,  g_srcs);
    cudaGetSymbolAddress((void**)&ws,    g_ws);
    cudaGetSymbolAddress((void**)&bsums, g_bsums);

    const int smem128 = 128 * 128 * 4 + 128 * 34 * 4;
    const int smem64  = 128 * 64 * 4  + 128 * 34 * 4;
    cudaFuncSetAttribute(gemm_kernel<128>, cudaFuncAttributeMaxDynamicSharedMemorySize, smem128);
    cudaFuncSetAttribute(gemm_kernel<64>,  cudaFuncAttributeMaxDynamicSharedMemorySize, smem64);

    // ---- CSR build: counting sort by dst ----
    const int M  = N + 1;
    const int SB = (M + SCAN_CHUNK - 1) / SCAN_CHUNK;   // 98 <= 128
    zero_kernel<<<(M + 255) / 256, 256>>>(rp, M);
    hist_kernel<<<(E + 255) / 256, 256>>>(dst, rp, E);
    scan1_kernel<<<SB, SCAN_CHUNK>>>(rp, bsums, M);
    scan2_kernel<<<1, 128>>>(bsums, SB);
    scan3_kernel<<<SB, SCAN_CHUNK>>>(rp, bsums, M);
    dis_kernel<<<(N + 255) / 256, 256>>>(rp, dis, N);
    cursor_kernel<<<(N + 255) / 256, 256>>>(rp, cur, N);
    bucket_kernel<<<(E + 255) / 256, 256>>>(src, dst, dis, cur, srcs, ws, E);

    const int gblocks = (N + 127) / 128;

    // ----- layer 1 -----
    gemm_kernel<128><<<gblocks, 256, smem128>>>(x, W0, t, N);
    aggregate_kernel<128><<<N, 128>>>(t, rp, srcs, ws, dis, b0, h, N);

    // ----- layer 2 -----
    gemm_kernel<128><<<gblocks, 256, smem128>>>(h, W1, t, N);
    aggregate_kernel<128><<<N, 128>>>(t, rp, srcs, ws, dis, b1, h, N);

    // ----- layer 3 + log_softmax -----
    gemm_kernel<64><<<gblocks, 256, smem64>>>(h, W2, t, N);
    aggregate_lsm_kernel<<<N, 64>>>(t, rp, srcs, ws, dis, b2, (float*)d_out, N);
}

// round 4
// speedup vs baseline: 1.5341x; 1.3894x over previous
#include <cuda_runtime.h>

// ---------------------------------------------------------------------------
// FCHCGNN: 3-layer GCN + log_softmax.
//   CSR build (counting sort by dst) -> per layer: T = X@W (f32x2 FFMA2 SGEMM,
//   conflict-free smem), warp-per-node segment reduction (no atomics), fused
//   self-loop+bias+relu; final layer fuses log_softmax.
// Launch order puts gemm1 at slot 4 so ncu profiles it.
// ---------------------------------------------------------------------------

#define NN_MAX 100000
#define EE_MAX 1600000
#define SCAN_CHUNK 1024

__device__ float g_t[(size_t)NN_MAX * 128];
__device__ float g_h[(size_t)NN_MAX * 128];
__device__ float g_dis[NN_MAX];
__device__ int   g_cnt[NN_MAX];
__device__ int   g_rowptr[NN_MAX + 1];
__device__ int   g_cursor[NN_MAX + 1];
__device__ int   g_srcs[EE_MAX];
__device__ float g_ws[EE_MAX];
__device__ int   g_bsums[128];

// --------------------------- CSR construction ------------------------------

__global__ void zero_kernel(int* __restrict__ cnt, int* __restrict__ rp,
                            int* __restrict__ cur, int n) {
    int i = blockIdx.x * blockDim.x + threadIdx.x;
    if (i < n) cnt[i] = 0;
    if (i == 0) { rp[0] = 0; cur[0] = 0; }
}

__global__ void hist_kernel(const int* __restrict__ dst, int* __restrict__ cnt, int e) {
    int i = blockIdx.x * blockDim.x + threadIdx.x;
    if (i < e) atomicAdd(&cnt[dst[i]], 1);
}

// per-chunk inclusive scan of cnt -> rp[i+1]; chunk totals to bsums
__global__ void scan1_kernel(const int* __restrict__ cnt, int* __restrict__ rp,
                             int* __restrict__ bsums, int m) {
    __shared__ int s[SCAN_CHUNK];
    int tid = threadIdx.x;
    int i = blockIdx.x * SCAN_CHUNK + tid;
    int v = (i < m) ? cnt[i] : 0;
    s[tid] = v;
    __syncthreads();
#pragma unroll
    for (int o = 1; o < SCAN_CHUNK; o <<= 1) {
        int t = 0;
        if (tid >= o) t = s[tid - o];
        __syncthreads();
        s[tid] += t;
        __syncthreads();
    }
    if (i < m) rp[i + 1] = s[tid];
    if (tid == SCAN_CHUNK - 1) bsums[blockIdx.x] = s[SCAN_CHUNK - 1];
}

__global__ void dis_kernel(const int* __restrict__ cnt, float* __restrict__ dis, int n) {
    int i = blockIdx.x * blockDim.x + threadIdx.x;
    if (i < n) dis[i] = rsqrtf((float)(cnt[i] + 1));  // +1 self-loop
}

// add preceding-chunk offsets (block-sum prefix computed in-block); init cursor
__global__ void scan3_kernel(int* __restrict__ rp, int* __restrict__ cur,
                             const int* __restrict__ bsums, int nb, int m) {
    __shared__ int sb[128];
    int t = threadIdx.x;
    if (t < 128) sb[t] = (t < nb) ? bsums[t] : 0;
    __syncthreads();
    int off = 0;
    for (int k = 0; k < blockIdx.x; k++) off += sb[k];
    int i = blockIdx.x * SCAN_CHUNK + t;
    if (i < m) {
        int v = rp[i + 1] + off;
        rp[i + 1] = v;
        cur[i + 1] = v;
    }
}

__global__ void bucket_kernel(const int* __restrict__ src, const int* __restrict__ dst,
                              const float* __restrict__ dis, int* __restrict__ cur,
                              int* __restrict__ srcs, float* __restrict__ ws, int e) {
    int i = blockIdx.x * blockDim.x + threadIdx.x;
    if (i < e) {
        int s = src[i], d = dst[i];
        int p = atomicAdd(&cur[d], 1);
        srcs[p] = s;
        ws[p] = dis[s] * dis[d];
    }
}

// ----------------------- SGEMM with packed f32x2 FMA ------------------------
// Block: 128 rows x FOUT cols, 256 threads. Thread (ty,tx): rows ty*8..+7
// (4 f32x2 row-pairs), cols tx+16j (interleaved -> conflict-free W loads).
// X chunk staged transposed Xt[k][row] (stride 130) -> LDS.64 pair loads.

template <int FOUT>
__global__ void gemm_kernel(const float* __restrict__ X, const float* __restrict__ W,
                            float* __restrict__ T, int n) {
    constexpr int KT = 32;
    constexpr int S  = 130;            // words, even stride, low-conflict
    constexpr int CPT = FOUT / 16;     // 8 or 4
    extern __shared__ float smem[];
    float* Ws = smem;                  // [128][FOUT]
    float* Xt = smem + 128 * FOUT;     // [KT][S]

    const int tid  = threadIdx.x;
    const int row0 = blockIdx.x * 128;

    for (int i = tid; i < 128 * FOUT / 4; i += 256)
        ((float4*)Ws)[i] = ((const float4*)W)[i];

    const int ty = tid >> 4;
    const int tx = tid & 15;

    unsigned long long acc[4][CPT];
#pragma unroll
    for (int p = 0; p < 4; p++)
#pragma unroll
        for (int j = 0; j < CPT; j++) acc[p][j] = 0ull;

#pragma unroll 1
    for (int k0 = 0; k0 < 128; k0 += KT) {
        __syncthreads();
#pragma unroll
        for (int i = tid; i < 128 * (KT / 4); i += 256) {
            int r = i >> 3, c4 = i & 7;
            int gr = row0 + r;
            float4 v = make_float4(0.f, 0.f, 0.f, 0.f);
            if (gr < n) v = *(const float4*)&X[(size_t)gr * 128 + k0 + c4 * 4];
            Xt[(c4 * 4 + 0) * S + r] = v.x;
            Xt[(c4 * 4 + 1) * S + r] = v.y;
            Xt[(c4 * 4 + 2) * S + r] = v.z;
            Xt[(c4 * 4 + 3) * S + r] = v.w;
        }
        __syncthreads();
#pragma unroll
        for (int kk = 0; kk < KT; kk++) {
            unsigned long long xp[4];
#pragma unroll
            for (int p = 0; p < 4; p++)
                xp[p] = *(const unsigned long long*)&Xt[kk * S + ty * 8 + 2 * p];
            const float* wrow = &Ws[(k0 + kk) * FOUT + tx];
#pragma unroll
            for (int j = 0; j < CPT; j++) {
                float w = wrow[16 * j];
                unsigned long long w2;
                asm("mov.b64 %0, {%1, %1};" : "=l"(w2) : "f"(w));
#pragma unroll
                for (int p = 0; p < 4; p++)
                    asm("fma.rn.f32x2 %0, %1, %2, %0;"
                        : "+l"(acc[p][j]) : "l"(xp[p]), "l"(w2));
            }
        }
    }

#pragma unroll
    for (int p = 0; p < 4; p++) {
        int r0 = row0 + ty * 8 + 2 * p;
        if (r0 < n) {
#pragma unroll
            for (int j = 0; j < CPT; j++) {
                float lo, hi;
                asm("mov.b64 {%0, %1}, %2;" : "=f"(lo), "=f"(hi) : "l"(acc[p][j]));
                T[(size_t)r0 * FOUT + tx + 16 * j] = lo;
                if (r0 + 1 < n)
                    T[(size_t)(r0 + 1) * FOUT + tx + 16 * j] = hi;
            }
        }
    }
}

// ---------------------- warp-per-node segment reduction ---------------------

__device__ __forceinline__ float4 fma4(float4 v, float w, float4 a) {
    a.x = fmaf(v.x, w, a.x); a.y = fmaf(v.y, w, a.y);
    a.z = fmaf(v.z, w, a.z); a.w = fmaf(v.w, w, a.w);
    return a;
}

__global__ void aggregate128_kernel(const float* __restrict__ T, const int* __restrict__ rp,
                                    const int* __restrict__ srcs, const float* __restrict__ ws,
                                    const float* __restrict__ dis, const float* __restrict__ bias,
                                    float* __restrict__ OUT, int n) {
    int node = blockIdx.x * 8 + (threadIdx.x >> 5);
    if (node >= n) return;
    int lane = threadIdx.x & 31;
    int beg = rp[node], end = rp[node + 1];

    float4 a0 = make_float4(0.f, 0.f, 0.f, 0.f), a1 = a0, a2 = a0, a3 = a0;
    for (int base = beg; base < end; base += 32) {
        int cnt = min(32, end - base);
        int s = 0; float w = 0.f;
        if (lane < cnt) { s = srcs[base + lane]; w = ws[base + lane]; }
        int j = 0;
        for (; j + 4 <= cnt; j += 4) {
            int   s0 = __shfl_sync(~0u, s, j),     s1 = __shfl_sync(~0u, s, j + 1);
            int   s2 = __shfl_sync(~0u, s, j + 2), s3 = __shfl_sync(~0u, s, j + 3);
            float w0 = __shfl_sync(~0u, w, j),     w1 = __shfl_sync(~0u, w, j + 1);
            float w2 = __shfl_sync(~0u, w, j + 2), w3 = __shfl_sync(~0u, w, j + 3);
            float4 v0 = *(const float4*)&T[(size_t)s0 * 128 + lane * 4];
            float4 v1 = *(const float4*)&T[(size_t)s1 * 128 + lane * 4];
            float4 v2 = *(const float4*)&T[(size_t)s2 * 128 + lane * 4];
            float4 v3 = *(const float4*)&T[(size_t)s3 * 128 + lane * 4];
            a0 = fma4(v0, w0, a0); a1 = fma4(v1, w1, a1);
            a2 = fma4(v2, w2, a2); a3 = fma4(v3, w3, a3);
        }
        for (; j < cnt; j++) {
            int   sj = __shfl_sync(~0u, s, j);
            float wj = __shfl_sync(~0u, w, j);
            a0 = fma4(*(const float4*)&T[(size_t)sj * 128 + lane * 4], wj, a0);
        }
    }
    float dd = dis[node], sn = dd * dd;
    float4 t = *(const float4*)&T[(size_t)node * 128 + lane * 4];
    float4 b = *(const float4*)&bias[lane * 4];
    float4 o;
    o.x = fmaxf(a0.x + a1.x + a2.x + a3.x + t.x * sn + b.x, 0.f);
    o.y = fmaxf(a0.y + a1.y + a2.y + a3.y + t.y * sn + b.y, 0.f);
    o.z = fmaxf(a0.z + a1.z + a2.z + a3.z + t.z * sn + b.z, 0.f);
    o.w = fmaxf(a0.w + a1.w + a2.w + a3.w + t.w * sn + b.w, 0.f);
    *(float4*)&OUT[(size_t)node * 128 + lane * 4] = o;
}

// Final layer (F=64): warp-per-node, float2/lane, fused relu + log_softmax.
__global__ void aggregate_lsm_kernel(const float* __restrict__ T, const int* __restrict__ rp,
                                     const int* __restrict__ srcs, const float* __restrict__ ws,
                                     const float* __restrict__ dis, const float* __restrict__ bias,
                                     float* __restrict__ OUT, int n) {
    int node = blockIdx.x * 8 + (threadIdx.x >> 5);
    if (node >= n) return;
    int lane = threadIdx.x & 31;
    int beg = rp[node], end = rp[node + 1];

    float2 a0 = make_float2(0.f, 0.f), a1 = a0, a2 = a0, a3 = a0;
    for (int base = beg; base < end; base += 32) {
        int cnt = min(32, end - base);
        int s = 0; float w = 0.f;
        if (lane < cnt) { s = srcs[base + lane]; w = ws[base + lane]; }
        int j = 0;
        for (; j + 4 <= cnt; j += 4) {
            int   s0 = __shfl_sync(~0u, s, j),     s1 = __shfl_sync(~0u, s, j + 1);
            int   s2 = __shfl_sync(~0u, s, j + 2), s3 = __shfl_sync(~0u, s, j + 3);
            float w0 = __shfl_sync(~0u, w, j),     w1 = __shfl_sync(~0u, w, j + 1);
            float w2 = __shfl_sync(~0u, w, j + 2), w3 = __shfl_sync(~0u, w, j + 3);
            float2 v0 = *(const float2*)&T[(size_t)s0 * 64 + lane * 2];
            float2 v1 = *(const float2*)&T[(size_t)s1 * 64 + lane * 2];
            float2 v2 = *(const float2*)&T[(size_t)s2 * 64 + lane * 2];
            float2 v3 = *(const float2*)&T[(size_t)s3 * 64 + lane * 2];
            a0.x = fmaf(v0.x, w0, a0.x); a0.y = fmaf(v0.y, w0, a0.y);
            a1.x = fmaf(v1.x, w1, a1.x); a1.y = fmaf(v1.y, w1, a1.y);
            a2.x = fmaf(v2.x, w2, a2.x); a2.y = fmaf(v2.y, w2, a2.y);
            a3.x = fmaf(v3.x, w3, a3.x); a3.y = fmaf(v3.y, w3, a3.y);
        }
        for (; j < cnt; j++) {
            int   sj = __shfl_sync(~0u, s, j);
            float wj = __shfl_sync(~0u, w, j);
            float2 v = *(const float2*)&T[(size_t)sj * 64 + lane * 2];
            a0.x = fmaf(v.x, wj, a0.x); a0.y = fmaf(v.y, wj, a0.y);
        }
    }
    float dd = dis[node], sn = dd * dd;
    float2 t = *(const float2*)&T[(size_t)node * 64 + lane * 2];
    float2 b = *(const float2*)&bias[lane * 2];
    float vx = fmaxf(a0.x + a1.x + a2.x + a3.x + t.x * sn + b.x, 0.f);
    float vy = fmaxf(a0.y + a1.y + a2.y + a3.y + t.y * sn + b.y, 0.f);

    float m = fmaxf(vx, vy);
#pragma unroll
    for (int o = 16; o; o >>= 1) m = fmaxf(m, __shfl_xor_sync(~0u, m, o));
    float sum = expf(vx - m) + expf(vy - m);
#pragma unroll
    for (int o = 16; o; o >>= 1) sum += __shfl_xor_sync(~0u, sum, o);
    float lse = m + logf(sum);
    float2 o2 = make_float2(vx - lse, vy - lse);
    *(float2*)&OUT[(size_t)node * 64 + lane * 2] = o2;
}

// --------------------------------- driver -----------------------------------

extern "C" void kernel_launch(void* const* d_in, const int* in_sizes, int n_in,
                              void* d_out, int out_size) {
    const float* x  = (const float*)d_in[0];
    const int*   ei = (const int*)d_in[1];
    const float* W0 = (const float*)d_in[2];
    const float* b0 = (const float*)d_in[3];
    const float* W1 = (const float*)d_in[4];
    const float* b1 = (const float*)d_in[5];
    const float* W2 = (const float*)d_in[6];
    const float* b2 = (const float*)d_in[7];

    const int N = in_sizes[0] / 128;
    const int E = in_sizes[1] / 2;
    const int* src = ei;
    const int* dst = ei + E;

    float *t, *h, *dis, *ws;
    int *cnt, *rp, *cur, *srcs, *bsums;
    cudaGetSymbolAddress((void**)&t,     g_t);
    cudaGetSymbolAddress((void**)&h,     g_h);
    cudaGetSymbolAddress((void**)&dis,   g_dis);
    cudaGetSymbolAddress((void**)&cnt,   g_cnt);
    cudaGetSymbolAddress((void**)&rp,    g_rowptr);
    cudaGetSymbolAddress((void**)&cur,   g_cursor);
    cudaGetSymbolAddress((void**)&srcs,  g_srcs);
    cudaGetSymbolAddress((void**)&ws,    g_ws);
    cudaGetSymbolAddress((void**)&bsums, g_bsums);

    const int smem128 = 128 * 128 * 4 + 32 * 130 * 4;  // 82176 B
    const int smem64  = 128 * 64 * 4  + 32 * 130 * 4;  // 49408 B
    cudaFuncSetAttribute(gemm_kernel<128>, cudaFuncAttributeMaxDynamicSharedMemorySize, smem128);
    cudaFuncSetAttribute(gemm_kernel<64>,  cudaFuncAttributeMaxDynamicSharedMemorySize, smem64);

    const int SB = (N + SCAN_CHUNK - 1) / SCAN_CHUNK;  // 98 <= 128
    const int gblocks = (N + 127) / 128;
    const int ablocks = (N + 7) / 8;

    // launches 1-3: CSR front half
    zero_kernel<<<(N + 255) / 256, 256>>>(cnt, rp, cur, N);
    hist_kernel<<<(E + 255) / 256, 256>>>(dst, cnt, E);
    scan1_kernel<<<SB, SCAN_CHUNK>>>(cnt, rp, bsums, N);

    // launch 4 (ncu-profiled): layer-1 GEMM (independent of CSR)
    gemm_kernel<128><<<gblocks, 256, smem128>>>(x, W0, t, N);

    // CSR back half
    dis_kernel<<<(N + 255) / 256, 256>>>(cnt, dis, N);
    scan3_kernel<<<SB, SCAN_CHUNK>>>(rp, cur, bsums, SB, N);
    bucket_kernel<<<(E + 255) / 256, 256>>>(src, dst, dis, cur, srcs, ws, E);

    // layer 1 aggregate
    aggregate128_kernel<<<ablocks, 256>>>(t, rp, srcs, ws, dis, b0, h, N);

    // layer 2
    gemm_kernel<128><<<gblocks, 256, smem128>>>(h, W1, t, N);
    aggregate128_kernel<<<ablocks, 256>>>(t, rp, srcs, ws, dis, b1, h, N);

    // layer 3 + log_softmax
    gemm_kernel<64><<<gblocks, 256, smem64>>>(h, W2, t, N);
    aggregate_lsm_kernel<<<ablocks, 256>>>(t, rp, srcs, ws, dis, b2, (float*)d_out, N);
}

// round 6
// speedup vs baseline: 1.5510x; 1.0110x over previous
#include <cuda_runtime.h>

// ---------------------------------------------------------------------------
// FCHCGNN: 3-layer GCN + log_softmax.
//   CSR build (counting sort by dst) -> per layer: T = X@W (f32x2 FFMA2 SGEMM,
//   4x8 thread tile, 32 warps/SM, pre-duplicated X in smem -> no pack MOVs),
//   warp-per-node segment reduction (no atomics), fused self-loop+bias+relu;
//   final layer fuses log_softmax. gemm1 stays at launch slot 4 for ncu.
// ---------------------------------------------------------------------------

#define NN_MAX 100000
#define EE_MAX 1600000
#define SCAN_CHUNK 1024

__device__ float g_t[(size_t)NN_MAX * 128];
__device__ float g_h[(size_t)NN_MAX * 128];
__device__ float g_dis[NN_MAX];
__device__ int   g_cnt[NN_MAX];
__device__ int   g_rowptr[NN_MAX + 1];
__device__ int   g_cursor[NN_MAX + 1];
__device__ int   g_srcs[EE_MAX];
__device__ float g_ws[EE_MAX];
__device__ int   g_bsums[128];

// --------------------------- CSR construction ------------------------------

__global__ void zero_kernel(int* __restrict__ cnt, int* __restrict__ rp,
                            int* __restrict__ cur, int n) {
    int i = blockIdx.x * blockDim.x + threadIdx.x;
    if (i < n) cnt[i] = 0;
    if (i == 0) { rp[0] = 0; cur[0] = 0; }
}

__global__ void hist_kernel(const int* __restrict__ dst, int* __restrict__ cnt, int e) {
    int i = blockIdx.x * blockDim.x + threadIdx.x;
    if (i < e) atomicAdd(&cnt[dst[i]], 1);
}

__global__ void scan1_kernel(const int* __restrict__ cnt, int* __restrict__ rp,
                             int* __restrict__ bsums, int m) {
    __shared__ int s[SCAN_CHUNK];
    int tid = threadIdx.x;
    int i = blockIdx.x * SCAN_CHUNK + tid;
    int v = (i < m) ? cnt[i] : 0;
    s[tid] = v;
    __syncthreads();
#pragma unroll
    for (int o = 1; o < SCAN_CHUNK; o <<= 1) {
        int t = 0;
        if (tid >= o) t = s[tid - o];
        __syncthreads();
        s[tid] += t;
        __syncthreads();
    }
    if (i < m) rp[i + 1] = s[tid];
    if (tid == SCAN_CHUNK - 1) bsums[blockIdx.x] = s[SCAN_CHUNK - 1];
}

__global__ void dis_kernel(const int* __restrict__ cnt, float* __restrict__ dis, int n) {
    int i = blockIdx.x * blockDim.x + threadIdx.x;
    if (i < n) dis[i] = rsqrtf((float)(cnt[i] + 1));
}

__global__ void scan3_kernel(int* __restrict__ rp, int* __restrict__ cur,
                             const int* __restrict__ bsums, int nb, int m) {
    __shared__ int sb[128];
    int t = threadIdx.x;
    if (t < 128) sb[t] = (t < nb) ? bsums[t] : 0;
    __syncthreads();
    int off = 0;
    for (int k = 0; k < blockIdx.x; k++) off += sb[k];
    int i = blockIdx.x * SCAN_CHUNK + t;
    if (i < m) {
        int v = rp[i + 1] + off;
        rp[i + 1] = v;
        cur[i + 1] = v;
    }
}

__global__ void bucket_kernel(const int* __restrict__ src, const int* __restrict__ dst,
                              const float* __restrict__ dis, int* __restrict__ cur,
                              int* __restrict__ srcs, float* __restrict__ ws, int e) {
    int i = blockIdx.x * blockDim.x + threadIdx.x;
    if (i < e) {
        int s = src[i], d = dst[i];
        int p = atomicAdd(&cur[d], 1);
        srcs[p] = s;
        ws[p] = dis[s] * dis[d];
    }
}

// ----------------------- SGEMM, f32x2, 4x8 thread tile ----------------------
// Block: 128 rows x FOUT cols, 512 threads (ty 0..31, tx 0..15).
// Thread: rows ty*4..+3, col pairs {2tx+32j, 2tx+32j+1}, j < FOUT/32.
// X staged DUPLICATED: Xd[k][2r]={x,x} -> broadcast LDS.64, no pack MOVs.
// W staged per k0-tile: Wt[32][FOUT]; col-pair LDS.64 conflict-free.

template <int FOUT>
__global__ __launch_bounds__(512, 2)
void gemm_kernel(const float* __restrict__ X, const float* __restrict__ W,
                 float* __restrict__ T, int n) {
    constexpr int KT  = 32;
    constexpr int XDS = 258;          // words per k-row of Xd (256 + 2 pad)
    constexpr int CP2 = FOUT / 32;    // col pairs per thread (4 or 2)
    extern __shared__ float smem[];
    float* Wt = smem;                 // [KT][FOUT]
    float* Xd = smem + KT * FOUT;     // [KT][XDS]

    const int tid  = threadIdx.x;
    const int row0 = blockIdx.x * 128;
    const int ty   = tid >> 4;        // 0..31
    const int tx   = tid & 15;        // 0..15

    unsigned long long acc[4][CP2];
#pragma unroll
    for (int i = 0; i < 4; i++)
#pragma unroll
        for (int j = 0; j < CP2; j++) acc[i][j] = 0ull;

#pragma unroll 1
    for (int k0 = 0; k0 < 128; k0 += KT) {
        __syncthreads();
        // stage W tile (rows k0..k0+31 are contiguous in W)
#pragma unroll
        for (int i = tid; i < KT * FOUT / 4; i += 512)
            ((float4*)Wt)[i] = ((const float4*)&W[(size_t)k0 * FOUT])[i];
        // stage X tile duplicated: 128 rows x 8 float4 chunks
#pragma unroll
        for (int idx = tid; idx < 128 * 8; idx += 512) {
            int r = idx >> 3, c4 = idx & 7;
            int gr = row0 + r;
            float4 v = make_float4(0.f, 0.f, 0.f, 0.f);
            if (gr < n) v = *(const float4*)&X[(size_t)gr * 128 + k0 + c4 * 4];
            *(float2*)&Xd[(c4 * 4 + 0) * XDS + 2 * r] = make_float2(v.x, v.x);
            *(float2*)&Xd[(c4 * 4 + 1) * XDS + 2 * r] = make_float2(v.y, v.y);
            *(float2*)&Xd[(c4 * 4 + 2) * XDS + 2 * r] = make_float2(v.z, v.z);
            *(float2*)&Xd[(c4 * 4 + 3) * XDS + 2 * r] = make_float2(v.w, v.w);
        }
        __syncthreads();
#pragma unroll
        for (int kk = 0; kk < KT; kk++) {
            unsigned long long xd[4], wp[CP2];
#pragma unroll
            for (int i = 0; i < 4; i++)
                xd[i] = *(const unsigned long long*)&Xd[kk * XDS + (ty * 4 + i) * 2];
#pragma unroll
            for (int j = 0; j < CP2; j++)
                wp[j] = *(const unsigned long long*)&Wt[kk * FOUT + 2 * tx + 32 * j];
#pragma unroll
            for (int i = 0; i < 4; i++)
#pragma unroll
                for (int j = 0; j < CP2; j++)
                    asm("fma.rn.f32x2 %0, %1, %2, %0;"
                        : "+l"(acc[i][j]) : "l"(xd[i]), "l"(wp[j]));
        }
    }

#pragma unroll
    for (int i = 0; i < 4; i++) {
        int gr = row0 + ty * 4 + i;
        if (gr < n) {
#pragma unroll
            for (int j = 0; j < CP2; j++) {
                float lo, hi;
                asm("mov.b64 {%0, %1}, %2;" : "=f"(lo), "=f"(hi) : "l"(acc[i][j]));
                *(float2*)&T[(size_t)gr * FOUT + 2 * tx + 32 * j] = make_float2(lo, hi);
            }
        }
    }
}

// ---------------------- warp-per-node segment reduction ---------------------

__device__ __forceinline__ float4 fma4(float4 v, float w, float4 a) {
    a.x = fmaf(v.x, w, a.x); a.y = fmaf(v.y, w, a.y);
    a.z = fmaf(v.z, w, a.z); a.w = fmaf(v.w, w, a.w);
    return a;
}

__global__ void aggregate128_kernel(const float* __restrict__ T, const int* __restrict__ rp,
                                    const int* __restrict__ srcs, const float* __restrict__ ws,
                                    const float* __restrict__ dis, const float* __restrict__ bias,
                                    float* __restrict__ OUT, int n) {
    int node = blockIdx.x * 8 + (threadIdx.x >> 5);
    if (node >= n) return;
    int lane = threadIdx.x & 31;
    int beg = rp[node], end = rp[node + 1];

    float4 a0 = make_float4(0.f, 0.f, 0.f, 0.f), a1 = a0, a2 = a0, a3 = a0;
    for (int base = beg; base < end; base += 32) {
        int cnt = min(32, end - base);
        int s = 0; float w = 0.f;
        if (lane < cnt) { s = srcs[base + lane]; w = ws[base + lane]; }
        int j = 0;
        for (; j + 4 <= cnt; j += 4) {
            int   s0 = __shfl_sync(~0u, s, j),     s1 = __shfl_sync(~0u, s, j + 1);
            int   s2 = __shfl_sync(~0u, s, j + 2), s3 = __shfl_sync(~0u, s, j + 3);
            float w0 = __shfl_sync(~0u, w, j),     w1 = __shfl_sync(~0u, w, j + 1);
            float w2 = __shfl_sync(~0u, w, j + 2), w3 = __shfl_sync(~0u, w, j + 3);
            float4 v0 = *(const float4*)&T[(size_t)s0 * 128 + lane * 4];
            float4 v1 = *(const float4*)&T[(size_t)s1 * 128 + lane * 4];
            float4 v2 = *(const float4*)&T[(size_t)s2 * 128 + lane * 4];
            float4 v3 = *(const float4*)&T[(size_t)s3 * 128 + lane * 4];
            a0 = fma4(v0, w0, a0); a1 = fma4(v1, w1, a1);
            a2 = fma4(v2, w2, a2); a3 = fma4(v3, w3, a3);
        }
        for (; j < cnt; j++) {
            int   sj = __shfl_sync(~0u, s, j);
            float wj = __shfl_sync(~0u, w, j);
            a0 = fma4(*(const float4*)&T[(size_t)sj * 128 + lane * 4], wj, a0);
        }
    }
    float dd = dis[node], sn = dd * dd;
    float4 t = *(const float4*)&T[(size_t)node * 128 + lane * 4];
    float4 b = *(const float4*)&bias[lane * 4];
    float4 o;
    o.x = fmaxf(a0.x + a1.x + a2.x + a3.x + t.x * sn + b.x, 0.f);
    o.y = fmaxf(a0.y + a1.y + a2.y + a3.y + t.y * sn + b.y, 0.f);
    o.z = fmaxf(a0.z + a1.z + a2.z + a3.z + t.z * sn + b.z, 0.f);
    o.w = fmaxf(a0.w + a1.w + a2.w + a3.w + t.w * sn + b.w, 0.f);
    *(float4*)&OUT[(size_t)node * 128 + lane * 4] = o;
}

__global__ void aggregate_lsm_kernel(const float* __restrict__ T, const int* __restrict__ rp,
                                     const int* __restrict__ srcs, const float* __restrict__ ws,
                                     const float* __restrict__ dis, const float* __restrict__ bias,
                                     float* __restrict__ OUT, int n) {
    int node = blockIdx.x * 8 + (threadIdx.x >> 5);
    if (node >= n) return;
    int lane = threadIdx.x & 31;
    int beg = rp[node], end = rp[node + 1];

    float2 a0 = make_float2(0.f, 0.f), a1 = a0, a2 = a0, a3 = a0;
    for (int base = beg; base < end; base += 32) {
        int cnt = min(32, end - base);
        int s = 0; float w = 0.f;
        if (lane < cnt) { s = srcs[base + lane]; w = ws[base + lane]; }
        int j = 0;
        for (; j + 4 <= cnt; j += 4) {
            int   s0 = __shfl_sync(~0u, s, j),     s1 = __shfl_sync(~0u, s, j + 1);
            int   s2 = __shfl_sync(~0u, s, j + 2), s3 = __shfl_sync(~0u, s, j + 3);
            float w0 = __shfl_sync(~0u, w, j),     w1 = __shfl_sync(~0u, w, j + 1);
            float w2 = __shfl_sync(~0u, w, j + 2), w3 = __shfl_sync(~0u, w, j + 3);
            float2 v0 = *(const float2*)&T[(size_t)s0 * 64 + lane * 2];
            float2 v1 = *(const float2*)&T[(size_t)s1 * 64 + lane * 2];
            float2 v2 = *(const float2*)&T[(size_t)s2 * 64 + lane * 2];
            float2 v3 = *(const float2*)&T[(size_t)s3 * 64 + lane * 2];
            a0.x = fmaf(v0.x, w0, a0.x); a0.y = fmaf(v0.y, w0, a0.y);
            a1.x = fmaf(v1.x, w1, a1.x); a1.y = fmaf(v1.y, w1, a1.y);
            a2.x = fmaf(v2.x, w2, a2.x); a2.y = fmaf(v2.y, w2, a2.y);
            a3.x = fmaf(v3.x, w3, a3.x); a3.y = fmaf(v3.y, w3, a3.y);
        }
        for (; j < cnt; j++) {
            int   sj = __shfl_sync(~0u, s, j);
            float wj = __shfl_sync(~0u, w, j);
            float2 v = *(const float2*)&T[(size_t)sj * 64 + lane * 2];
            a0.x = fmaf(v.x, wj, a0.x); a0.y = fmaf(v.y, wj, a0.y);
        }
    }
    float dd = dis[node], sn = dd * dd;
    float2 t = *(const float2*)&T[(size_t)node * 64 + lane * 2];
    float2 b = *(const float2*)&bias[lane * 2];
    float vx = fmaxf(a0.x + a1.x + a2.x + a3.x + t.x * sn + b.x, 0.f);
    float vy = fmaxf(a0.y + a1.y + a2.y + a3.y + t.y * sn + b.y, 0.f);

    float m = fmaxf(vx, vy);
#pragma unroll
    for (int o = 16; o; o >>= 1) m = fmaxf(m, __shfl_xor_sync(~0u, m, o));
    float sum = expf(vx - m) + expf(vy - m);
#pragma unroll
    for (int o = 16; o; o >>= 1) sum += __shfl_xor_sync(~0u, sum, o);
    float lse = m + logf(sum);
    *(float2*)&OUT[(size_t)node * 64 + lane * 2] = make_float2(vx - lse, vy - lse);
}

// --------------------------------- driver -----------------------------------

extern "C" void kernel_launch(void* const* d_in, const int* in_sizes, int n_in,
                              void* d_out, int out_size) {
    const float* x  = (const float*)d_in[0];
    const int*   ei = (const int*)d_in[1];
    const float* W0 = (const float*)d_in[2];
    const float* b0 = (const float*)d_in[3];
    const float* W1 = (const float*)d_in[4];
    const float* b1 = (const float*)d_in[5];
    const float* W2 = (const float*)d_in[6];
    const float* b2 = (const float*)d_in[7];

    const int N = in_sizes[0] / 128;
    const int E = in_sizes[1] / 2;
    const int* src = ei;
    const int* dst = ei + E;

    float *t, *h, *dis, *ws;
    int *cnt, *rp, *cur, *srcs, *bsums;
    cudaGetSymbolAddress((void**)&t,     g_t);
    cudaGetSymbolAddress((void**)&h,     g_h);
    cudaGetSymbolAddress((void**)&dis,   g_dis);
    cudaGetSymbolAddress((void**)&cnt,   g_cnt);
    cudaGetSymbolAddress((void**)&rp,    g_rowptr);
    cudaGetSymbolAddress((void**)&cur,   g_cursor);
    cudaGetSymbolAddress((void**)&srcs,  g_srcs);
    cudaGetSymbolAddress((void**)&ws,    g_ws);
    cudaGetSymbolAddress((void**)&bsums, g_bsums);

    const int smem128 = 32 * 128 * 4 + 32 * 258 * 4;  // 49408 B
    const int smem64  = 32 * 64 * 4  + 32 * 258 * 4;  // 41216 B
    cudaFuncSetAttribute(gemm_kernel<128>, cudaFuncAttributeMaxDynamicSharedMemorySize, smem128);
    cudaFuncSetAttribute(gemm_kernel<64>,  cudaFuncAttributeMaxDynamicSharedMemorySize, smem64);

    const int SB = (N + SCAN_CHUNK - 1) / SCAN_CHUNK;
    const int gblocks = (N + 127) / 128;
    const int ablocks = (N + 7) / 8;

    // launches 1-3: CSR front half
    zero_kernel<<<(N + 255) / 256, 256>>>(cnt, rp, cur, N);
    hist_kernel<<<(E + 255) / 256, 256>>>(dst, cnt, E);
    scan1_kernel<<<SB, SCAN_CHUNK>>>(cnt, rp, bsums, N);

    // launch 4 (ncu-profiled): layer-1 GEMM
    gemm_kernel<128><<<gblocks, 512, smem128>>>(x, W0, t, N);

    // CSR back half
    dis_kernel<<<(N + 255) / 256, 256>>>(cnt, dis, N);
    scan3_kernel<<<SB, SCAN_CHUNK>>>(rp, cur, bsums, SB, N);
    bucket_kernel<<<(E + 255) / 256, 256>>>(src, dst, dis, cur, srcs, ws, E);

    // layer 1 aggregate
    aggregate128_kernel<<<ablocks, 256>>>(t, rp, srcs, ws, dis, b0, h, N);

    // layer 2
    gemm_kernel<128><<<gblocks, 512, smem128>>>(h, W1, t, N);
    aggregate128_kernel<<<ablocks, 256>>>(t, rp, srcs, ws, dis, b1, h, N);

    // layer 3 + log_softmax
    gemm_kernel<64><<<gblocks, 512, smem64>>>(h, W2, t, N);
    aggregate_lsm_kernel<<<ablocks, 256>>>(t, rp, srcs, ws, dis, b2, (float*)d_out, N);
}